// round 13
// baseline (speedup 1.0000x reference)
#include <cuda_runtime.h>
#include <cstdint>

#define TT 128
#define BB 512
#define EE 128
#define NEVT 16
#define NBC 16              // batches per CTA (2 groups of 8)
#define NBLK (BB / NBC)     // 32 CTAs
#define L2E 1.4426950408889634f
#define LN2 0.6931471805599453f
#define NEGL2 (-10000.0f * L2E)

__device__ float g_partial[BB];
__device__ unsigned g_done;     // zero-init; restored each launch

// ---------------------------------------------------------------------------
__device__ __forceinline__ float ex2(float x) {
    float r; asm("ex2.approx.ftz.f32 %0, %1;" : "=f"(r) : "f"(x)); return r;
}
__device__ __forceinline__ float lg2(float x) {
    float r; asm("lg2.approx.ftz.f32 %0, %1;" : "=f"(r) : "f"(x)); return r;
}
__device__ __forceinline__ uint32_t totf32(float x) {
    uint32_t r; asm("cvt.rna.tf32.f32 %0, %1;" : "=r"(r) : "f"(x)); return r;
}
__device__ __forceinline__ void mma8(float& c0, float& c1, float& c2, float& c3,
                                     uint32_t a0, uint32_t a1, uint32_t a2,
                                     uint32_t a3, uint32_t b0, uint32_t b1) {
    asm volatile(
        "mma.sync.aligned.m16n8k8.row.col.f32.tf32.tf32.f32 "
        "{%0,%1,%2,%3}, {%4,%5,%6,%7}, {%8,%9}, {%0,%1,%2,%3};"
        : "+f"(c0), "+f"(c1), "+f"(c2), "+f"(c3)
        : "r"(a0), "r"(a1), "r"(a2), "r"(a3), "r"(b0), "r"(b1));
}

// ---------------------------------------------------------------------------
// 512 threads = 2 independent batch-groups of 8 warps. Warp lw of group gi
// owns rows 16lw..16lw+15 for batches b0 + 8gi + 0..7. Per step: 16 chained
// m16n8k8 tf32 MMAs (Q stationary in A-fragments), P through smem (conflict-
// free), double buffered, ONE barrier covers both groups. 4 warps/SMSP hide
// each other's LDS/HMMA/barrier latency (R12 measured 2 warps/SMSP -> issue
// 29%, step ~1100cy; the kernel is exposed-latency-bound).
// Normalizer G(b) = fv[row 17][b] lagged 2 steps (3-slot rotation): exact lse,
// no reductions in the loop. Boundary partials y*2^(mt+tl), combined at end.
// ---------------------------------------------------------------------------
__global__ void __launch_bounds__(512)
crf_kernel(const float* __restrict__ feats, const float* __restrict__ trans,
           float* __restrict__ out, int nblocks) {
    const int tid = threadIdx.x;
    const int w = tid >> 5, lane = tid & 31;
    const int gi = w >> 3, lw = w & 7;          // group, warp-in-group
    const int g = lane >> 2, tig = lane & 3;
    const int r0 = 16 * lw + g, r1 = r0 + 8;
    const int bA = 2 * tig, bB = bA + 1;
    const int b0g = blockIdx.x * NBC + gi * 8;  // group's first batch

    __shared__ __align__(16) float Pbuf[2][2][EE * 8];  // [group][parity][j*8+b]
    __shared__ float slot[2][3][8];                     // [group] G rotation
    __shared__ float bwp[2][NEVT][8][8];                // boundary partials
    __shared__ float gsv[2][NEVT][8];                   // Gc at each event
    __shared__ float mt2s[EE], tl2s[EE];
    __shared__ float rsum[16];
    __shared__ unsigned slast;

    // ---- feat prefetch pointers: (r0,bA),(r0,bB),(r1,bA),(r1,bB) ----
    const size_t tstr = (size_t)BB * EE;
    const float* fpp[4];
    fpp[0] = feats + (size_t)(b0g + bA) * EE + r0;
    fpp[1] = feats + (size_t)(b0g + bB) * EE + r0;
    fpp[2] = fpp[0] + 8;
    fpp[3] = fpp[1] + 8;
    float f1[4], fcur[4], fnx[4], fnew[4];
#pragma unroll
    for (int i = 0; i < 4; i++) f1[i]   = fpp[i][tstr];
#pragma unroll
    for (int i = 0; i < 4; i++) fcur[i] = fpp[i][2 * tstr];
#pragma unroll
    for (int i = 0; i < 4; i++) fnx[i]  = fpp[i][3 * tstr];
#pragma unroll
    for (int i = 0; i < 4; i++) fnew[i] = fnx[i];

    // ---- row maxes + last-row transitions (log2 units) ----
    if (tid < EE) {
        const float4* rp = (const float4*)(trans + tid * EE);
        float m = -3.4e38f;
#pragma unroll
        for (int i = 0; i < 32; i++) {
            float4 v = rp[i];
            m = fmaxf(m, fmaxf(fmaxf(v.x, v.y), fmaxf(v.z, v.w)));
        }
        mt2s[tid] = m * L2E;
        tl2s[tid] = trans[(EE - 1) * EE + tid] * L2E;
    }
    if (tid < 16)   // preinit G slot[2] for both groups
        slot[tid >> 3][2][tid & 7] =
            (blockIdx.x * NBC + tid == 0) ? 0.0f : NEGL2;
    __syncthreads();

    const float mtA = mt2s[r0], mtB = mt2s[r1];
    const float etlA = ex2(mtA + tl2s[r0]);
    const float etlB = ex2(mtB + tl2s[r1]);

    // ---- stationary A fragments: Q rows r0,r1 (log2 domain, tf32) ----
    uint32_t a[16][4];
#pragma unroll
    for (int s = 0; s < 16; s++) {
        int k0 = 8 * s + tig, k2 = k0 + 4;
        a[s][0] = totf32(ex2(fmaf(trans[r0 * EE + k0], L2E, -mtA)));
        a[s][1] = totf32(ex2(fmaf(trans[r1 * EE + k0], L2E, -mtB)));
        a[s][2] = totf32(ex2(fmaf(trans[r0 * EE + k2], L2E, -mtA)));
        a[s][3] = totf32(ex2(fmaf(trans[r1 * EE + k2], L2E, -mtB)));
    }

    float Gc[2];
    Gc[0] = (b0g + bA == 0) ? 0.0f : NEGL2;
    Gc[1] = NEGL2;                     // b0g + bB >= 1 always

    // P_0 = 2^(f(t=1)*L2E)
    {
        float* P0 = Pbuf[gi][0];
        P0[r0 * 8 + bA] = ex2(f1[0] * L2E);
        P0[r0 * 8 + bB] = ex2(f1[1] * L2E);
        P0[r1 * 8 + bA] = ex2(f1[2] * L2E);
        P0[r1 * 8 + bB] = ex2(f1[3] * L2E);
    }
    __syncthreads();

#pragma unroll 1
    for (int u = 0; u < 112; u++) {
        // ---- shadow: normalizer + ec for P_{u+1}, feat prefetch ----
        const int ri = (u + 2) % 3;
        float Gn0 = slot[gi][ri][bA], Gn1 = slot[gi][ri][bB];
        float ec[4];
        ec[0] = ex2(fmaf(fcur[0], L2E, Gc[0] + mtA - Gn0));
        ec[1] = ex2(fmaf(fcur[1], L2E, Gc[1] + mtA - Gn1));
        ec[2] = ex2(fmaf(fcur[2], L2E, Gc[0] + mtB - Gn0));
        ec[3] = ex2(fmaf(fcur[3], L2E, Gc[1] + mtB - Gn1));
        if (u <= 108) {
            size_t off = (size_t)(u + 4 + (u + 3) / 7) * tstr;   // t(u+3)
#pragma unroll
            for (int i = 0; i < 4; i++) fnew[i] = fpp[i][off];
        }

        // ---- tensor matvec: 16 HMMA, 4 independent accumulator chains ----
        const float* PB = Pbuf[gi][u & 1];
        float c[4][4];
#pragma unroll
        for (int qq = 0; qq < 4; qq++)
#pragma unroll
            for (int i = 0; i < 4; i++) c[qq][i] = 0.0f;
#pragma unroll
        for (int s = 0; s < 16; s++) {
            uint32_t bv0 = __float_as_uint(PB[(8 * s + tig) * 8 + g]);
            uint32_t bv1 = __float_as_uint(PB[(8 * s + tig + 4) * 8 + g]);
            mma8(c[s & 3][0], c[s & 3][1], c[s & 3][2], c[s & 3][3],
                 a[s][0], a[s][1], a[s][2], a[s][3], bv0, bv1);
        }
        float y0 = (c[0][0] + c[1][0]) + (c[2][0] + c[3][0]);  // (r0,bA)
        float y1 = (c[0][1] + c[1][1]) + (c[2][1] + c[3][1]);  // (r0,bB)
        float y2 = (c[0][2] + c[1][2]) + (c[2][2] + c[3][2]);  // (r1,bA)
        float y3 = (c[0][3] + c[1][3]) + (c[2][3] + c[3][3]);  // (r1,bB)

        // ---- P_{u+1} = y * ec ----
        if (u < 111) {
            float* PW = Pbuf[gi][(u + 1) & 1];
            *(float2*)&PW[r0 * 8 + bA] = make_float2(y0 * ec[0], y1 * ec[1]);
            *(float2*)&PW[r1 * 8 + bA] = make_float2(y2 * ec[2], y3 * ec[3]);
        }

        // ---- publish G (row 17 = lw 1, g 1, r0 path) per group ----
        if (lw == 1 && g == 1) {
            slot[gi][u % 3][bA] = Gc[0] + mtA + lg2(y0);
            slot[gi][u % 3][bB] = Gc[1] + mtA + lg2(y1);
        }

        // ---- boundary lse partials (every 7th step, e = u/7) ----
        if ((u % 7) == 6) {
            int e = u / 7;
            float sA = fmaf(y0, etlA, y2 * etlB);
            float sB = fmaf(y1, etlA, y3 * etlB);
            sA += __shfl_xor_sync(0xffffffffu, sA, 4);
            sB += __shfl_xor_sync(0xffffffffu, sB, 4);
            sA += __shfl_xor_sync(0xffffffffu, sA, 8);
            sB += __shfl_xor_sync(0xffffffffu, sB, 8);
            sA += __shfl_xor_sync(0xffffffffu, sA, 16);
            sB += __shfl_xor_sync(0xffffffffu, sB, 16);
            if (lane < 4) {
                bwp[gi][e][lw][bA] = sA;
                bwp[gi][e][lw][bB] = sB;
                if (lw == 0) { gsv[gi][e][bA] = Gc[0]; gsv[gi][e][bB] = Gc[1]; }
            }
        }

        __syncthreads();
        Gc[0] = Gn0; Gc[1] = Gn1;
#pragma unroll
        for (int i = 0; i < 4; i++) { fcur[i] = fnx[i]; fnx[i] = fnew[i]; }
    }

    // ---- combine 16 events x 16 batches ----
    if (tid < 256) {
        int e = tid & 15, bb = tid >> 4;       // bb = 0..15
        int gg = bb >> 3, b = bb & 7;
        float s8 = 0.0f;
#pragma unroll
        for (int ww = 0; ww < 8; ww++) s8 += bwp[gg][e][ww][b];
        float val = gsv[gg][e][b] + lg2(s8);
#pragma unroll
        for (int o = 1; o < 16; o <<= 1)
            val += __shfl_xor_sync(0xffffffffu, val, o);
        if (e == 0) g_partial[blockIdx.x * NBC + bb] = val * LN2;
    }

    // ---- fused final reduction (last CTA of 32) ----
    __threadfence();
    __syncthreads();
    if (tid == 0) {
        unsigned v = atomicAdd(&g_done, 1u);
        slast = (v == (unsigned)(nblocks - 1)) ? 1u : 0u;
    }
    __syncthreads();
    if (slast) {
        __threadfence();
        float v = __ldcg(&g_partial[tid]);     // 512 threads = 512 partials
#pragma unroll
        for (int o = 16; o; o >>= 1) v += __shfl_xor_sync(0xffffffffu, v, o);
        if (lane == 0) rsum[w] = v;
        __syncthreads();
        if (tid == 0) {
            float tot = 0.0f;
#pragma unroll
            for (int ww = 0; ww < 16; ww++) tot += rsum[ww];
            out[0] = tot * (1.0f / (float)(BB * NEVT));
            g_done = 0;                        // restore for next graph replay
        }
    }
}

// ---------------------------------------------------------------------------
extern "C" void kernel_launch(void* const* d_in, const int* in_sizes, int n_in,
                              void* d_out, int out_size) {
    const float* feats = (const float*)d_in[0];
    const float* trans = (const float*)d_in[1];
    if (n_in >= 2 && in_sizes[0] == EE * EE) {   // defensive order check
        feats = (const float*)d_in[1];
        trans = (const float*)d_in[0];
    }
    crf_kernel<<<NBLK, 512>>>(feats, trans, (float*)d_out, NBLK);
}

// round 14
// speedup vs baseline: 2.4225x; 2.4225x over previous
#include <cuda_runtime.h>
#include <cstdint>

#define TT 128
#define BB 512
#define EE 128
#define NEVT 16
#define NBC 8               // batches per CTA
#define NBLK (BB / NBC)     // 64 CTAs
#define L2E 1.4426950408889634f
#define LN2 0.6931471805599453f
#define NEGL2 (-10000.0f * L2E)
#define PPAR 1280           // floats per P parity buffer (2 x 32 rows x 20)

__device__ float g_partial[BB];
__device__ unsigned g_done;     // zero-init; restored each launch

// ---------------------------------------------------------------------------
__device__ __forceinline__ float ex2(float x) {
    float r; asm("ex2.approx.ftz.f32 %0, %1;" : "=f"(r) : "f"(x)); return r;
}
__device__ __forceinline__ float lg2(float x) {
    float r; asm("lg2.approx.ftz.f32 %0, %1;" : "=f"(r) : "f"(x)); return r;
}
__device__ __forceinline__ uint32_t totf32(float x) {
    uint32_t r; asm("cvt.rna.tf32.f32 %0, %1;" : "=r"(r) : "f"(x)); return r;
}
__device__ __forceinline__ void mma8(float& c0, float& c1, float& c2, float& c3,
                                     uint32_t a0, uint32_t a1, uint32_t a2,
                                     uint32_t a3, uint32_t b0, uint32_t b1) {
    asm volatile(
        "mma.sync.aligned.m16n8k8.row.col.f32.tf32.tf32.f32 "
        "{%0,%1,%2,%3}, {%4,%5,%6,%7}, {%8,%9}, {%0,%1,%2,%3};"
        : "+f"(c0), "+f"(c1), "+f"(c2), "+f"(c3)
        : "r"(a0), "r"(a1), "r"(a2), "r"(a3), "r"(b0), "r"(b1));
}

// ---------------------------------------------------------------------------
// R12 structure (64 CTAs x 256 threads, warp w owns rows 16w..16w+15, cols =
// 8 batches, Q stationary in A-fragments, 16 chained m16n8k8 tf32 MMAs/step).
// R14 change: P is stored FRAGMENT-MAJOR — P[k][n] lives at row q=4n+(k&3)
// (+PB2 half for k&7>=4), col s=k>>3, row stride 20 floats. Each thread's 32
// B-fragment values are 2 contiguous 16-float rows at q==lane: 8 LDS.128
// (conflict-free, front-batched) instead of 32 scattered LDS.32.
// Normalizer G(b) = fv[row 17][b] lagged 2 steps (3-slot rotation): exact lse,
// no reductions in the loop. Boundary partials y*2^(mt+tl), combined at end.
// ---------------------------------------------------------------------------
__global__ void __launch_bounds__(256)
crf_kernel(const float* __restrict__ feats, const float* __restrict__ trans,
           float* __restrict__ out, int nblocks) {
    const int tid = threadIdx.x;
    const int w = tid >> 5, lane = tid & 31;
    const int g = lane >> 2, tig = lane & 3;
    const int r0 = 16 * w + g, r1 = r0 + 8;
    const int bA = 2 * tig, bB = bA + 1;
    const int b0 = blockIdx.x * NBC;

    __shared__ __align__(16) float PQ[2][PPAR];   // [parity][PA(640) | PB2(640)]
    __shared__ float slot[3][NBC];                // G rotation
    __shared__ float bwp[NEVT][8][NBC];           // boundary partials
    __shared__ float gsv[NEVT][NBC];              // Gc at each event
    __shared__ float mt2s[EE], tl2s[EE];
    __shared__ float rsum[8];
    __shared__ unsigned slast;

    // ---- feat prefetch pointers: (r0,bA),(r0,bB),(r1,bA),(r1,bB) ----
    const size_t tstr = (size_t)BB * EE;
    const float* fpp[4];
    fpp[0] = feats + (size_t)(b0 + bA) * EE + r0;
    fpp[1] = feats + (size_t)(b0 + bB) * EE + r0;
    fpp[2] = fpp[0] + 8;
    fpp[3] = fpp[1] + 8;
    float f1[4], fcur[4], fnx[4], fnew[4];
#pragma unroll
    for (int i = 0; i < 4; i++) f1[i]   = fpp[i][tstr];
#pragma unroll
    for (int i = 0; i < 4; i++) fcur[i] = fpp[i][2 * tstr];
#pragma unroll
    for (int i = 0; i < 4; i++) fnx[i]  = fpp[i][3 * tstr];
#pragma unroll
    for (int i = 0; i < 4; i++) fnew[i] = fnx[i];

    // ---- row maxes + last-row transitions (log2 units) ----
    if (tid < EE) {
        const float4* rp = (const float4*)(trans + tid * EE);
        float m = -3.4e38f;
#pragma unroll
        for (int i = 0; i < 32; i++) {
            float4 v = rp[i];
            m = fmaxf(m, fmaxf(fmaxf(v.x, v.y), fmaxf(v.z, v.w)));
        }
        mt2s[tid] = m * L2E;
        tl2s[tid] = trans[(EE - 1) * EE + tid] * L2E;
    }
    if (tid < NBC)      // preinit G slot[2] (= G_1 = fv_init)
        slot[2][tid] = (b0 + tid == 0) ? 0.0f : NEGL2;
    __syncthreads();

    const float mtA = mt2s[r0], mtB = mt2s[r1];
    const float etlA = ex2(mtA + tl2s[r0]);
    const float etlB = ex2(mtB + tl2s[r1]);

    // ---- stationary A fragments: Q rows r0,r1 (log2 domain, tf32) ----
    uint32_t a[16][4];
#pragma unroll
    for (int s = 0; s < 16; s++) {
        int k0 = 8 * s + tig, k2 = k0 + 4;
        a[s][0] = totf32(ex2(fmaf(trans[r0 * EE + k0], L2E, -mtA)));
        a[s][1] = totf32(ex2(fmaf(trans[r1 * EE + k0], L2E, -mtB)));
        a[s][2] = totf32(ex2(fmaf(trans[r0 * EE + k2], L2E, -mtA)));
        a[s][3] = totf32(ex2(fmaf(trans[r1 * EE + k2], L2E, -mtB)));
    }

    float Gc[2];
    Gc[0] = (b0 + bA == 0) ? 0.0f : NEGL2;
    Gc[1] = NEGL2;                      // b0 + bB >= 1 always

    // Writer base offsets (fragment-major layout):
    //   half = (g<4) ? PA(0) : PB2(640);  row qa=4*bA+(g&3), qb=4*bB+(g&3)
    //   col pair s = {2w, 2w+1}  (r0>>3 = 2w, r1>>3 = 2w+1)
    const int whalf = (g < 4) ? 0 : 640;
    const int wqa = (4 * bA + (g & 3)) * 20 + 2 * w;
    const int wqb = (4 * bB + (g & 3)) * 20 + 2 * w;

    // P_0 = 2^(f(t=1)*L2E)
    *(float2*)&PQ[0][whalf + wqa] = make_float2(ex2(f1[0] * L2E), ex2(f1[2] * L2E));
    *(float2*)&PQ[0][whalf + wqb] = make_float2(ex2(f1[1] * L2E), ex2(f1[3] * L2E));
    __syncthreads();

#pragma unroll 1
    for (int u = 0; u < 112; u++) {
        // ---- front-batched B-fragment loads: 8x LDS.128, own row q==lane ----
        const float* PBb = PQ[u & 1];
        const float4* ra = (const float4*)(PBb + lane * 20);         // bv0[s]
        const float4* rb = (const float4*)(PBb + 640 + lane * 20);   // bv1[s]
        float bva[16], bvb[16];
        *(float4*)&bva[0]  = ra[0]; *(float4*)&bva[4]  = ra[1];
        *(float4*)&bva[8]  = ra[2]; *(float4*)&bva[12] = ra[3];
        *(float4*)&bvb[0]  = rb[0]; *(float4*)&bvb[4]  = rb[1];
        *(float4*)&bvb[8]  = rb[2]; *(float4*)&bvb[12] = rb[3];

        // ---- shadow: normalizer + ec for P_{u+1}, feat prefetch ----
        const int ri = (u + 2) % 3;
        float Gn0 = slot[ri][bA], Gn1 = slot[ri][bB];
        float ec[4];
        ec[0] = ex2(fmaf(fcur[0], L2E, Gc[0] + mtA - Gn0));
        ec[1] = ex2(fmaf(fcur[1], L2E, Gc[1] + mtA - Gn1));
        ec[2] = ex2(fmaf(fcur[2], L2E, Gc[0] + mtB - Gn0));
        ec[3] = ex2(fmaf(fcur[3], L2E, Gc[1] + mtB - Gn1));
        if (u <= 108) {
            size_t off = (size_t)(u + 4 + (u + 3) / 7) * tstr;   // t(u+3)
#pragma unroll
            for (int i = 0; i < 4; i++) fnew[i] = fpp[i][off];
        }

        // ---- tensor matvec: 16 HMMA, 4 independent accumulator chains ----
        float c[4][4];
#pragma unroll
        for (int qq = 0; qq < 4; qq++)
#pragma unroll
            for (int i = 0; i < 4; i++) c[qq][i] = 0.0f;
#pragma unroll
        for (int s = 0; s < 16; s++) {
            mma8(c[s & 3][0], c[s & 3][1], c[s & 3][2], c[s & 3][3],
                 a[s][0], a[s][1], a[s][2], a[s][3],
                 __float_as_uint(bva[s]), __float_as_uint(bvb[s]));
        }
        float y0 = (c[0][0] + c[1][0]) + (c[2][0] + c[3][0]);  // (r0,bA)
        float y1 = (c[0][1] + c[1][1]) + (c[2][1] + c[3][1]);  // (r0,bB)
        float y2 = (c[0][2] + c[1][2]) + (c[2][2] + c[3][2]);  // (r1,bA)
        float y3 = (c[0][3] + c[1][3]) + (c[2][3] + c[3][3]);  // (r1,bB)

        // ---- P_{u+1} = y * ec (fragment-major, 2x STS.64) ----
        if (u < 111) {
            float* PW = PQ[(u + 1) & 1] + whalf;
            *(float2*)&PW[wqa] = make_float2(y0 * ec[0], y2 * ec[2]);
            *(float2*)&PW[wqb] = make_float2(y1 * ec[1], y3 * ec[3]);
        }

        // ---- publish G (row 17 = warp 1, g==1, r0 path) ----
        if (w == 1 && g == 1) {
            slot[u % 3][bA] = Gc[0] + mtA + lg2(y0);
            slot[u % 3][bB] = Gc[1] + mtA + lg2(y1);
        }

        // ---- boundary lse partials (every 7th step, e = u/7) ----
        if ((u % 7) == 6) {
            int e = u / 7;
            float sA = fmaf(y0, etlA, y2 * etlB);   // batch bA: 2^(fv+tl-Gc)
            float sB = fmaf(y1, etlA, y3 * etlB);   // batch bB
            sA += __shfl_xor_sync(0xffffffffu, sA, 4);
            sB += __shfl_xor_sync(0xffffffffu, sB, 4);
            sA += __shfl_xor_sync(0xffffffffu, sA, 8);
            sB += __shfl_xor_sync(0xffffffffu, sB, 8);
            sA += __shfl_xor_sync(0xffffffffu, sA, 16);
            sB += __shfl_xor_sync(0xffffffffu, sB, 16);
            if (lane < 4) {             // lane == tig here
                bwp[e][w][bA] = sA;
                bwp[e][w][bB] = sB;
                if (w == 0) { gsv[e][bA] = Gc[0]; gsv[e][bB] = Gc[1]; }
            }
        }

        __syncthreads();
        Gc[0] = Gn0; Gc[1] = Gn1;
#pragma unroll
        for (int i = 0; i < 4; i++) { fcur[i] = fnx[i]; fnx[i] = fnew[i]; }
    }

    // ---- combine 16 events x 8 batches ----
    if (tid < 128) {
        int e = tid & 15, b = tid >> 4;
        float s8 = 0.0f;
#pragma unroll
        for (int ww = 0; ww < 8; ww++) s8 += bwp[e][ww][b];
        float val = gsv[e][b] + lg2(s8);
#pragma unroll
        for (int o = 1; o < 16; o <<= 1)
            val += __shfl_xor_sync(0xffffffffu, val, o);
        if (e == 0) g_partial[b0 + b] = val * LN2;
    }

    // ---- fused final reduction (last CTA) ----
    __threadfence();
    __syncthreads();
    if (tid == 0) {
        unsigned v = atomicAdd(&g_done, 1u);
        slast = (v == (unsigned)(nblocks - 1)) ? 1u : 0u;
    }
    __syncthreads();
    if (slast) {
        __threadfence();
        float v = __ldcg(&g_partial[tid]) + __ldcg(&g_partial[tid + 256]);
#pragma unroll
        for (int o = 16; o; o >>= 1) v += __shfl_xor_sync(0xffffffffu, v, o);
        if (lane == 0) rsum[w] = v;
        __syncthreads();
        if (tid == 0) {
            float tot = 0.0f;
#pragma unroll
            for (int ww = 0; ww < 8; ww++) tot += rsum[ww];
            out[0] = tot * (1.0f / (float)(BB * NEVT));
            g_done = 0;                 // restore for next graph replay
        }
    }
}

// ---------------------------------------------------------------------------
extern "C" void kernel_launch(void* const* d_in, const int* in_sizes, int n_in,
                              void* d_out, int out_size) {
    const float* feats = (const float*)d_in[0];
    const float* trans = (const float*)d_in[1];
    if (n_in >= 2 && in_sizes[0] == EE * EE) {   // defensive order check
        feats = (const float*)d_in[1];
        trans = (const float*)d_in[0];
    }
    crf_kernel<<<NBLK, 256>>>(feats, trans, (float*)d_out, NBLK);
}

// round 15
// speedup vs baseline: 2.7894x; 1.1515x over previous
#include <cuda_runtime.h>
#include <cstdint>

#define TT 128
#define BB 512
#define EE 128
#define NEVT 16
#define NBC 8               // batches per CTA
#define NBLK (BB / NBC)     // 64 CTAs
#define L2E 1.4426950408889634f
#define LN2 0.6931471805599453f
#define NEGL2 (-10000.0f * L2E)

__device__ float g_partial[BB];
__device__ unsigned g_done;     // zero-init; restored each launch

// ---------------------------------------------------------------------------
__device__ __forceinline__ float ex2(float x) {
    float r; asm("ex2.approx.ftz.f32 %0, %1;" : "=f"(r) : "f"(x)); return r;
}
__device__ __forceinline__ float lg2(float x) {
    float r; asm("lg2.approx.ftz.f32 %0, %1;" : "=f"(r) : "f"(x)); return r;
}
__device__ __forceinline__ uint32_t packbf(float lo, float hi) {   // {hi:lo} bf16x2
    uint32_t r;
    asm("cvt.rn.satfinite.bf16x2.f32 %0, %1, %2;" : "=r"(r) : "f"(hi), "f"(lo));
    return r;
}
// m16n8k16 bf16 HMMA (sm_80+ baseline; fine on plain sm_103 target)
__device__ __forceinline__ void mma16(float& c0, float& c1, float& c2, float& c3,
                                      uint32_t a0, uint32_t a1, uint32_t a2,
                                      uint32_t a3, uint32_t b0, uint32_t b1) {
    asm volatile(
        "mma.sync.aligned.m16n8k16.row.col.f32.bf16.bf16.f32 "
        "{%0,%1,%2,%3}, {%4,%5,%6,%7}, {%8,%9}, {%0,%1,%2,%3};"
        : "+f"(c0), "+f"(c1), "+f"(c2), "+f"(c3)
        : "r"(a0), "r"(a1), "r"(a2), "r"(a3), "r"(b0), "r"(b1));
}

// ---------------------------------------------------------------------------
// R12 structure (64 CTAs x 256 threads; warp w owns rows 16w..16w+15, cols =
// the 8 batches; Q stationary in A-fragments) with bf16 m16n8k16:
//   - 8 HMMAs/step (4 chains x 2 deep) instead of 16 (4x4)
//   - P stored as bf16x2 over j-pairs: word P2[j>>1][b]; 16 LDS.32/thread/step
//     (conflict-free: bank = (8*tig + g) & 31, distinct across the warp)
//   - writer: y*ec -> 4 shfl(xor 4) pairs -> cvt.bf16x2 -> 2 STS.64 (even-g
//     lanes), banks verified conflict-free
// Normalizer G(b) = fv[row 17][b] lagged 2 steps (3-slot rotation): exact lse,
// no reductions in the loop. Boundary partials y*2^(mt+tl), combined at end.
// ---------------------------------------------------------------------------
__global__ void __launch_bounds__(256)
crf_kernel(const float* __restrict__ feats, const float* __restrict__ trans,
           float* __restrict__ out, int nblocks) {
    const int tid = threadIdx.x;
    const int w = tid >> 5, lane = tid & 31;
    const int g = lane >> 2, tig = lane & 3;
    const int r0 = 16 * w + g, r1 = r0 + 8;
    const int bA = 2 * tig, bB = bA + 1;
    const int b0 = blockIdx.x * NBC;

    __shared__ __align__(16) uint32_t P2[2][512];   // [parity][(j>>1)*8 + b]
    __shared__ float slot[3][NBC];                  // G rotation
    __shared__ float bwp[NEVT][8][NBC];             // boundary partials
    __shared__ float gsv[NEVT][NBC];                // Gc at each event
    __shared__ float mt2s[EE], tl2s[EE];
    __shared__ float rsum[8];
    __shared__ unsigned slast;

    // ---- feat prefetch pointers: (r0,bA),(r0,bB),(r1,bA),(r1,bB) ----
    const size_t tstr = (size_t)BB * EE;
    const float* fpp[4];
    fpp[0] = feats + (size_t)(b0 + bA) * EE + r0;
    fpp[1] = feats + (size_t)(b0 + bB) * EE + r0;
    fpp[2] = fpp[0] + 8;
    fpp[3] = fpp[1] + 8;
    float f1[4], fcur[4], fnx[4], fnew[4];
#pragma unroll
    for (int i = 0; i < 4; i++) f1[i]   = fpp[i][tstr];
#pragma unroll
    for (int i = 0; i < 4; i++) fcur[i] = fpp[i][2 * tstr];
#pragma unroll
    for (int i = 0; i < 4; i++) fnx[i]  = fpp[i][3 * tstr];
#pragma unroll
    for (int i = 0; i < 4; i++) fnew[i] = fnx[i];

    // ---- row maxes + last-row transitions (log2 units) ----
    if (tid < EE) {
        const float4* rp = (const float4*)(trans + tid * EE);
        float m = -3.4e38f;
#pragma unroll
        for (int i = 0; i < 32; i++) {
            float4 v = rp[i];
            m = fmaxf(m, fmaxf(fmaxf(v.x, v.y), fmaxf(v.z, v.w)));
        }
        mt2s[tid] = m * L2E;
        tl2s[tid] = trans[(EE - 1) * EE + tid] * L2E;
    }
    if (tid < NBC)      // preinit G slot[2] (= G_1 = fv_init)
        slot[2][tid] = (b0 + tid == 0) ? 0.0f : NEGL2;
    __syncthreads();

    const float mtA = mt2s[r0], mtB = mt2s[r1];
    const float etlA = ex2(mtA + tl2s[r0]);
    const float etlB = ex2(mtB + tl2s[r1]);

    // ---- stationary A fragments (bf16): Q rows r0,r1, K-chunks of 16 ----
    uint32_t a[8][4];
#pragma unroll
    for (int s = 0; s < 8; s++) {
        int k0 = 16 * s + 2 * tig;
        float qA0 = ex2(fmaf(trans[r0 * EE + k0],     L2E, -mtA));
        float qA1 = ex2(fmaf(trans[r0 * EE + k0 + 1], L2E, -mtA));
        float qB0 = ex2(fmaf(trans[r1 * EE + k0],     L2E, -mtB));
        float qB1 = ex2(fmaf(trans[r1 * EE + k0 + 1], L2E, -mtB));
        float qA8 = ex2(fmaf(trans[r0 * EE + k0 + 8], L2E, -mtA));
        float qA9 = ex2(fmaf(trans[r0 * EE + k0 + 9], L2E, -mtA));
        float qB8 = ex2(fmaf(trans[r1 * EE + k0 + 8], L2E, -mtB));
        float qB9 = ex2(fmaf(trans[r1 * EE + k0 + 9], L2E, -mtB));
        a[s][0] = packbf(qA0, qA1);
        a[s][1] = packbf(qB0, qB1);
        a[s][2] = packbf(qA8, qA9);
        a[s][3] = packbf(qB8, qB9);
    }

    float Gc[2];
    Gc[0] = (b0 + bA == 0) ? 0.0f : NEGL2;
    Gc[1] = NEGL2;                      // b0 + bB >= 1 always

    // ---- P_0 = 2^(f(t=1)*L2E), packed bf16x2 over j-pairs ----
    {
        float p0 = ex2(f1[0] * L2E), p1 = ex2(f1[1] * L2E);
        float p2 = ex2(f1[2] * L2E), p3 = ex2(f1[3] * L2E);
        float q0 = __shfl_xor_sync(0xffffffffu, p0, 4);
        float q1 = __shfl_xor_sync(0xffffffffu, p1, 4);
        float q2 = __shfl_xor_sync(0xffffffffu, p2, 4);
        float q3 = __shfl_xor_sync(0xffffffffu, p3, 4);
        if (!(lane & 4)) {              // even g: own j even, partner j = j+1
            *(uint2*)&P2[0][(r0 >> 1) * 8 + bA] =
                make_uint2(packbf(p0, q0), packbf(p1, q1));
            *(uint2*)&P2[0][(r1 >> 1) * 8 + bA] =
                make_uint2(packbf(p2, q2), packbf(p3, q3));
        }
    }
    __syncthreads();

#pragma unroll 1
    for (int u = 0; u < 112; u++) {
        // ---- front-batched B-fragment loads: 16x LDS.32, conflict-free ----
        const uint32_t* PB = P2[u & 1];
        uint32_t bv0[8], bv1[8];
#pragma unroll
        for (int s = 0; s < 8; s++) {
            bv0[s] = PB[64 * s + 8 * tig + g];          // k = 16s+2tig(+1)
            bv1[s] = PB[64 * s + 32 + 8 * tig + g];     // k = 16s+8+2tig(+1)
        }

        // ---- shadow: normalizer + ec for P_{u+1}, feat prefetch ----
        const int ri = (u + 2) % 3;
        float Gn0 = slot[ri][bA], Gn1 = slot[ri][bB];
        float ec[4];
        ec[0] = ex2(fmaf(fcur[0], L2E, Gc[0] + mtA - Gn0));
        ec[1] = ex2(fmaf(fcur[1], L2E, Gc[1] + mtA - Gn1));
        ec[2] = ex2(fmaf(fcur[2], L2E, Gc[0] + mtB - Gn0));
        ec[3] = ex2(fmaf(fcur[3], L2E, Gc[1] + mtB - Gn1));
        if (u <= 108) {
            size_t off = (size_t)(u + 4 + (u + 3) / 7) * tstr;   // t(u+3)
#pragma unroll
            for (int i = 0; i < 4; i++) fnew[i] = fpp[i][off];
        }

        // ---- tensor matvec: 8 HMMA, 4 chains x 2 deep ----
        float c[4][4];
#pragma unroll
        for (int qq = 0; qq < 4; qq++)
#pragma unroll
            for (int i = 0; i < 4; i++) c[qq][i] = 0.0f;
#pragma unroll
        for (int s = 0; s < 8; s++) {
            mma16(c[s & 3][0], c[s & 3][1], c[s & 3][2], c[s & 3][3],
                  a[s][0], a[s][1], a[s][2], a[s][3], bv0[s], bv1[s]);
        }
        float y0 = (c[0][0] + c[1][0]) + (c[2][0] + c[3][0]);  // (r0,bA)
        float y1 = (c[0][1] + c[1][1]) + (c[2][1] + c[3][1]);  // (r0,bB)
        float y2 = (c[0][2] + c[1][2]) + (c[2][2] + c[3][2]);  // (r1,bA)
        float y3 = (c[0][3] + c[1][3]) + (c[2][3] + c[3][3]);  // (r1,bB)

        // ---- P_{u+1} = y * ec (bf16x2 pack over j-pairs) ----
        if (u < 111) {
            float p0 = y0 * ec[0], p1 = y1 * ec[1];
            float p2 = y2 * ec[2], p3 = y3 * ec[3];
            float q0 = __shfl_xor_sync(0xffffffffu, p0, 4);
            float q1 = __shfl_xor_sync(0xffffffffu, p1, 4);
            float q2 = __shfl_xor_sync(0xffffffffu, p2, 4);
            float q3 = __shfl_xor_sync(0xffffffffu, p3, 4);
            if (!(lane & 4)) {
                uint32_t* PW = P2[(u + 1) & 1];
                *(uint2*)&PW[(r0 >> 1) * 8 + bA] =
                    make_uint2(packbf(p0, q0), packbf(p1, q1));
                *(uint2*)&PW[(r1 >> 1) * 8 + bA] =
                    make_uint2(packbf(p2, q2), packbf(p3, q3));
            }
        }

        // ---- publish G (row 17 = warp 1, g==1, r0 path) ----
        if (w == 1 && g == 1) {
            slot[u % 3][bA] = Gc[0] + mtA + lg2(y0);
            slot[u % 3][bB] = Gc[1] + mtA + lg2(y1);
        }

        // ---- boundary lse partials (every 7th step, e = u/7) ----
        if ((u % 7) == 6) {
            int e = u / 7;
            float sA = fmaf(y0, etlA, y2 * etlB);   // batch bA: 2^(fv+tl-Gc)
            float sB = fmaf(y1, etlA, y3 * etlB);   // batch bB
            sA += __shfl_xor_sync(0xffffffffu, sA, 4);
            sB += __shfl_xor_sync(0xffffffffu, sB, 4);
            sA += __shfl_xor_sync(0xffffffffu, sA, 8);
            sB += __shfl_xor_sync(0xffffffffu, sB, 8);
            sA += __shfl_xor_sync(0xffffffffu, sA, 16);
            sB += __shfl_xor_sync(0xffffffffu, sB, 16);
            if (lane < 4) {             // lane == tig here
                bwp[e][w][bA] = sA;
                bwp[e][w][bB] = sB;
                if (w == 0) { gsv[e][bA] = Gc[0]; gsv[e][bB] = Gc[1]; }
            }
        }

        __syncthreads();
        Gc[0] = Gn0; Gc[1] = Gn1;
#pragma unroll
        for (int i = 0; i < 4; i++) { fcur[i] = fnx[i]; fnx[i] = fnew[i]; }
    }

    // ---- combine 16 events x 8 batches ----
    if (tid < 128) {
        int e = tid & 15, b = tid >> 4;
        float s8 = 0.0f;
#pragma unroll
        for (int ww = 0; ww < 8; ww++) s8 += bwp[e][ww][b];
        float val = gsv[e][b] + lg2(s8);
#pragma unroll
        for (int o = 1; o < 16; o <<= 1)
            val += __shfl_xor_sync(0xffffffffu, val, o);
        if (e == 0) g_partial[b0 + b] = val * LN2;
    }

    // ---- fused final reduction (last CTA) ----
    __threadfence();
    __syncthreads();
    if (tid == 0) {
        unsigned v = atomicAdd(&g_done, 1u);
        slast = (v == (unsigned)(nblocks - 1)) ? 1u : 0u;
    }
    __syncthreads();
    if (slast) {
        __threadfence();
        float v = __ldcg(&g_partial[tid]) + __ldcg(&g_partial[tid + 256]);
#pragma unroll
        for (int o = 16; o; o >>= 1) v += __shfl_xor_sync(0xffffffffu, v, o);
        if (lane == 0) rsum[w] = v;
        __syncthreads();
        if (tid == 0) {
            float tot = 0.0f;
#pragma unroll
            for (int ww = 0; ww < 8; ww++) tot += rsum[ww];
            out[0] = tot * (1.0f / (float)(BB * NEVT));
            g_done = 0;                 // restore for next graph replay
        }
    }
}

// ---------------------------------------------------------------------------
extern "C" void kernel_launch(void* const* d_in, const int* in_sizes, int n_in,
                              void* d_out, int out_size) {
    const float* feats = (const float*)d_in[0];
    const float* trans = (const float*)d_in[1];
    if (n_in >= 2 && in_sizes[0] == EE * EE) {   // defensive order check
        feats = (const float*)d_in[1];
        trans = (const float*)d_in[0];
    }
    crf_kernel<<<NBLK, 256>>>(feats, trans, (float*)d_out, NBLK);
}